// round 16
// baseline (speedup 1.0000x reference)
#include <cuda_runtime.h>
#include <math.h>

#define T_ALL 128
#define T_STEPS 127
#define BSZ 256
#define DD 512
#define HH 1024
#define OO 20
#define KC 320
#define HSLICES 16                 // h-slices of 64 columns
#define NBG 8                      // batch groups of 32 rows
#define BPB 32                     // batch rows per block

__device__ __constant__ float c_ALPHA = 0.95122942450071400909f; // fp32(exp(-1/20))
__device__ __constant__ float c_KAPPA = 0.95122942450071400909f;
#define THRv 1.0f

// ---- scratch (device globals) ----
__device__ float    g_xin[(size_t)T_STEPS * BSZ * HH];
__device__ float    g_WT[HH * HH];            // WT[j][h], diag zeroed
__device__ float    g_WoT[HH * OO];           // WoT[h][o]
__device__ unsigned g_zbits[2][BSZ][HH / 32]; // spike bitmasks, parity-buffered
__device__ float    g_vopart[2][BSZ][HSLICES][OO];
__device__ int      g_bar[NBG];
__device__ int      g_bar2;

#define FMA2(d_, a_, b_) \
    asm("fma.rn.f32x2 %0, %1, %2, %3;" : "=l"(d_) : "l"(a_), "l"(b_), "l"(d_))
#define PACK2(d_, x_) \
    asm("mov.b64 %0, {%1, %1};" : "=l"(d_) : "f"(x_))

__device__ __forceinline__ float2 unpack2(unsigned long long u) {
    float2 f;
    asm("mov.b64 {%0, %1}, %2;" : "=f"(f.x), "=f"(f.y) : "l"(u));
    return f;
}

__global__ void dummy_k() {}

// ============================================================
__global__ void __launch_bounds__(256) prep_k(const float* __restrict__ w_rec,
                                              const float* __restrict__ w_out) {
    int idx = blockIdx.x * 256 + threadIdx.x;
    int stride = gridDim.x * 256;
    for (int i = idx; i < HH * HH; i += stride) {
        int j = i / HH, h = i % HH;
        g_WT[i] = (h == j) ? 0.0f : w_rec[(size_t)h * HH + j];
    }
    for (int i = idx; i < HH * OO; i += stride) {
        int h = i / OO, o = i % OO;
        g_WoT[i] = w_out[(size_t)o * HH + h];
    }
}

// ============================================================
__global__ void __launch_bounds__(256) init_k(float* __restrict__ out) {
    int i = blockIdx.x * blockDim.x + threadIdx.x;
    int stride = gridDim.x * blockDim.x;
    for (int idx = i; idx < BSZ * (HH / 32); idx += stride)
        ((unsigned*)g_zbits[0])[idx] = 0u;
    for (int idx = i; idx < BSZ * OO; idx += stride)
        out[idx] = 0.f;                                // row t=0
    if (i < NBG) g_bar[i] = 0;
    if (i == NBG) g_bar2 = 0;
}

// ============================================================
// input GEMM (R12, proven: bit-exact ascending-k chain, kc=320 fold)
// ============================================================
__global__ void __launch_bounds__(256) in_gemm(const float* __restrict__ x,
                                               const float* __restrict__ w_in) {
    __shared__ __align__(16) float As[2][8][128];
    __shared__ __align__(16) float Bs[2][8][128];
    const int tid = threadIdx.x;
    const int m0 = blockIdx.y * 128;
    const int n0 = blockIdx.x * 128;

    const int lr = tid >> 1;
    const int lk = (tid & 1) * 4;
    const int tm = (tid >> 4) * 4;
    const int tn = (tid & 15) * 4;

    const float* Ap = x + (size_t)(m0 + lr) * DD + lk;
    const float* Bp = w_in + (size_t)(n0 + lr) * DD + lk;

    float4 a  = __ldcs((const float4*)Ap);
    float4 bb = *(const float4*)Bp;
    As[0][lk + 0][lr] = a.x;  As[0][lk + 1][lr] = a.y;
    As[0][lk + 2][lr] = a.z;  As[0][lk + 3][lr] = a.w;
    Bs[0][lk + 0][lr] = bb.x; Bs[0][lk + 1][lr] = bb.y;
    Bs[0][lk + 2][lr] = bb.z; Bs[0][lk + 3][lr] = bb.w;
    __syncthreads();

    unsigned long long acc2[8][4];
#pragma unroll
    for (int i = 0; i < 8; i++)
#pragma unroll
        for (int j = 0; j < 4; j++) acc2[i][j] = 0ULL;

    int s = 0;
    for (int k0 = 0; k0 < DD; k0 += 8) {
        const int nk = k0 + 8;
        if (nk < DD) {
            a  = __ldcs((const float4*)(Ap + nk));
            bb = *(const float4*)(Bp + nk);
        }
#pragma unroll
        for (int d = 0; d < 8; d++) {
            float4 alo = *(const float4*)(&As[s][d][tm]);
            float4 ahi = *(const float4*)(&As[s][d][tm + 64]);
            ulonglong2 bl = *(const ulonglong2*)(&Bs[s][d][tn]);
            ulonglong2 bh = *(const ulonglong2*)(&Bs[s][d][tn + 64]);
            unsigned long long aa[8], bv[4] = {bl.x, bl.y, bh.x, bh.y};
            PACK2(aa[0], alo.x); PACK2(aa[1], alo.y);
            PACK2(aa[2], alo.z); PACK2(aa[3], alo.w);
            PACK2(aa[4], ahi.x); PACK2(aa[5], ahi.y);
            PACK2(aa[6], ahi.z); PACK2(aa[7], ahi.w);
#pragma unroll
            for (int i = 0; i < 8; i++)
#pragma unroll
                for (int j = 0; j < 4; j++)
                    FMA2(acc2[i][j], aa[i], bv[j]);
        }
        if (nk == KC) {
#pragma unroll
            for (int i = 0; i < 8; i++) {
                const int mr = m0 + tm + (i & 3) + ((i >> 2) << 6);
                float2 u0 = unpack2(acc2[i][0]), u1 = unpack2(acc2[i][1]);
                float2 u2 = unpack2(acc2[i][2]), u3 = unpack2(acc2[i][3]);
                float* dst = g_xin + (size_t)mr * HH + n0 + tn;
                *(float4*)dst        = make_float4(u0.x, u0.y, u1.x, u1.y);
                *(float4*)(dst + 64) = make_float4(u2.x, u2.y, u3.x, u3.y);
#pragma unroll
                for (int j = 0; j < 4; j++) acc2[i][j] = 0ULL;
            }
        }
        if (nk < DD) {
            As[s ^ 1][lk + 0][lr] = a.x;  As[s ^ 1][lk + 1][lr] = a.y;
            As[s ^ 1][lk + 2][lr] = a.z;  As[s ^ 1][lk + 3][lr] = a.w;
            Bs[s ^ 1][lk + 0][lr] = bb.x; Bs[s ^ 1][lk + 1][lr] = bb.y;
            Bs[s ^ 1][lk + 2][lr] = bb.z; Bs[s ^ 1][lk + 3][lr] = bb.w;
        }
        __syncthreads();
        s ^= 1;
    }

#pragma unroll
    for (int i = 0; i < 8; i++) {
        const int mr = m0 + tm + (i & 3) + ((i >> 2) << 6);
        float* dst = g_xin + (size_t)mr * HH + n0 + tn;
        float4 p0 = *(const float4*)dst;
        float4 p1 = *(const float4*)(dst + 64);
        float2 u0 = unpack2(acc2[i][0]), u1 = unpack2(acc2[i][1]);
        float2 u2 = unpack2(acc2[i][2]), u3 = unpack2(acc2[i][3]);
        float4 o0, o1;
        o0.x = __fadd_rn(p0.x, u0.x); o0.y = __fadd_rn(p0.y, u0.y);
        o0.z = __fadd_rn(p0.z, u1.x); o0.w = __fadd_rn(p0.w, u1.y);
        o1.x = __fadd_rn(p1.x, u2.x); o1.y = __fadd_rn(p1.y, u2.y);
        o1.z = __fadd_rn(p1.z, u3.x); o1.w = __fadd_rn(p1.w, u3.y);
        __stcs((float4*)dst, o0);
        __stcs((float4*)(dst + 64), o1);
    }
}

// ============================================================
// h-sliced persistent step kernel: 128 blocks = 16 hslices x 8 bgroups.
// Block owns WT[:, hs*64 .. hs*64+64) (256KB, L1-hot) for 32 batch rows.
// warp w: b_locals {w, w+16}; lane: 2 h-cols (h = hs*64 + lane*2).
// Gather = ascending bitmask walk, panel folds at words 10/20/30
// (== j 320/640/960) -> bit-exact chains. z exchanged via L2 bitmasks
// + per-bg 16-block spin barrier each step.
// ============================================================
__global__ void __launch_bounds__(512) step_all(float* __restrict__ out) {
    const int bid = blockIdx.x;
    const int hs = bid & (HSLICES - 1);
    const int bg = bid >> 4;
    const int tid = threadIdx.x;
    const int lane = tid & 31, w = tid >> 5;

    const int h0 = hs * 64 + lane * 2;
    const int b0g = bg * BPB + w;            // warp's first batch row
    const int b1g = b0g + 16;                // second

    __shared__ unsigned s_zw[BPB][33];       // padded bitmasks

    float v00 = 0.f, v01 = 0.f, v10 = 0.f, v11 = 0.f;
    float vo = 0.f;                          // owner state (warps 0,1, lane<OO)

    const int b_own = bg * BPB + hs + (w ? 16 : 0);   // valid for w<2

    static const int pw[5] = {0, 10, 20, 30, 32};

    for (int t = 0; t < T_STEPS; t++) {
        // load this step's z bitmasks (L2, parity-buffered; bypass L1)
        for (int i = tid; i < BPB * 32; i += 512) {
            int bl = i >> 5, wd = i & 31;
            s_zw[bl][wd] = __ldcg(&g_zbits[t & 1][bg * BPB + bl][wd]);
        }
        __syncthreads();

        // hoisted xin loads
        const float* xb = g_xin + (size_t)t * BSZ * HH;
        float2 xi0 = __ldcs((const float2*)(xb + (size_t)b0g * HH + h0));
        float2 xi1 = __ldcs((const float2*)(xb + (size_t)b1g * HH + h0));

        // ---- gather (exact ascending chains, panel folds) ----
        float t00 = 0.f, t01 = 0.f, t10 = 0.f, t11 = 0.f;
#pragma unroll
        for (int p = 0; p < 4; p++) {
            float a00 = 0.f, a01 = 0.f, a10 = 0.f, a11 = 0.f;
            for (int wd = pw[p]; wd < pw[p + 1]; wd++) {
                const int base = wd * 32;
                unsigned m0 = s_zw[w][wd];
                while (m0) {
                    int i0 = __ffs(m0) - 1; m0 &= m0 - 1;
                    if (m0) {
                        int i1 = __ffs(m0) - 1; m0 &= m0 - 1;
                        float2 w0 = *(const float2*)(g_WT + (size_t)(base + i0) * HH + h0);
                        float2 w1 = *(const float2*)(g_WT + (size_t)(base + i1) * HH + h0);
                        a00 = __fadd_rn(a00, w0.x); a01 = __fadd_rn(a01, w0.y);
                        a00 = __fadd_rn(a00, w1.x); a01 = __fadd_rn(a01, w1.y);
                    } else {
                        float2 w0 = *(const float2*)(g_WT + (size_t)(base + i0) * HH + h0);
                        a00 = __fadd_rn(a00, w0.x); a01 = __fadd_rn(a01, w0.y);
                    }
                }
                unsigned m1 = s_zw[w + 16][wd];
                while (m1) {
                    int i0 = __ffs(m1) - 1; m1 &= m1 - 1;
                    if (m1) {
                        int i1 = __ffs(m1) - 1; m1 &= m1 - 1;
                        float2 w0 = *(const float2*)(g_WT + (size_t)(base + i0) * HH + h0);
                        float2 w1 = *(const float2*)(g_WT + (size_t)(base + i1) * HH + h0);
                        a10 = __fadd_rn(a10, w0.x); a11 = __fadd_rn(a11, w0.y);
                        a10 = __fadd_rn(a10, w1.x); a11 = __fadd_rn(a11, w1.y);
                    } else {
                        float2 w0 = *(const float2*)(g_WT + (size_t)(base + i0) * HH + h0);
                        a10 = __fadd_rn(a10, w0.x); a11 = __fadd_rn(a11, w0.y);
                    }
                }
            }
            t00 = __fadd_rn(t00, a00); t01 = __fadd_rn(t01, a01);
            t10 = __fadd_rn(t10, a10); t11 = __fadd_rn(t11, a11);
        }

        // ---- v updates (identical arithmetic to R12) ----
        const float zp00 = (v00 > THRv) ? 1.f : 0.f;
        const float zp01 = (v01 > THRv) ? 1.f : 0.f;
        const float zp10 = (v10 > THRv) ? 1.f : 0.f;
        const float zp11 = (v11 > THRv) ? 1.f : 0.f;
        v00 = __fsub_rn(__fadd_rn(__fmaf_rn(c_ALPHA, v00, t00), xi0.x), zp00);
        v01 = __fsub_rn(__fadd_rn(__fmaf_rn(c_ALPHA, v01, t01), xi0.y), zp01);
        v10 = __fsub_rn(__fadd_rn(__fmaf_rn(c_ALPHA, v10, t10), xi1.x), zp10);
        v11 = __fsub_rn(__fadd_rn(__fmaf_rn(c_ALPHA, v11, t11), xi1.y), zp11);

        const bool z00 = v00 > THRv, z01 = v01 > THRv;
        const bool z10 = v10 > THRv, z11 = v11 > THRv;

        // ---- assemble slice z-words (2 bits/lane, OR-reduce per 16-half) ----
        unsigned c0 = ((z00 ? 1u : 0u) | (z01 ? 2u : 0u)) << ((lane & 15) * 2);
        unsigned c1 = ((z10 ? 1u : 0u) | (z11 ? 2u : 0u)) << ((lane & 15) * 2);
#pragma unroll
        for (int off = 1; off < 16; off <<= 1) {
            c0 |= __shfl_xor_sync(0xffffffffu, c0, off);
            c1 |= __shfl_xor_sync(0xffffffffu, c1, off);
        }
        if (lane == 0) {
            g_zbits[(t + 1) & 1][b0g][2 * hs + 0] = c0;
            g_zbits[(t + 1) & 1][b1g][2 * hs + 0] = c1;
        }
        if (lane == 16) {
            g_zbits[(t + 1) & 1][b0g][2 * hs + 1] = c0;
            g_zbits[(t + 1) & 1][b1g][2 * hs + 1] = c1;
        }

        // ---- per-slice vo partials (order-free path) ----
        unsigned wA0 = __shfl_sync(0xffffffffu, c0, 0);
        unsigned wB0 = __shfl_sync(0xffffffffu, c0, 16);
        unsigned wA1 = __shfl_sync(0xffffffffu, c1, 0);
        unsigned wB1 = __shfl_sync(0xffffffffu, c1, 16);
        if (lane < OO) {
            float acc0 = 0.f, acc1 = 0.f;
            unsigned m = wA0;
            while (m) { int b_ = __ffs(m) - 1; m &= m - 1;
                acc0 += g_WoT[(hs * 64 + b_) * OO + lane]; }
            m = wB0;
            while (m) { int b_ = __ffs(m) - 1; m &= m - 1;
                acc0 += g_WoT[(hs * 64 + 32 + b_) * OO + lane]; }
            m = wA1;
            while (m) { int b_ = __ffs(m) - 1; m &= m - 1;
                acc1 += g_WoT[(hs * 64 + b_) * OO + lane]; }
            m = wB1;
            while (m) { int b_ = __ffs(m) - 1; m &= m - 1;
                acc1 += g_WoT[(hs * 64 + 32 + b_) * OO + lane]; }
            g_vopart[t & 1][b0g][hs][lane] = acc0;
            g_vopart[t & 1][b1g][hs][lane] = acc1;
        }

        // ---- per-bg barrier (16 blocks) ----
        __threadfence();
        __syncthreads();
        if (tid == 0) {
            atomicAdd(&g_bar[bg], 1);
            while (((volatile int*)g_bar)[bg] < HSLICES * (t + 1)) __nanosleep(100);
            __threadfence();
        }
        __syncthreads();

        // ---- owner folds vo partials (ascending hs -> deterministic) ----
        if (w < 2 && lane < OO) {
            float dot = 0.f;
#pragma unroll
            for (int h2 = 0; h2 < HSLICES; h2++)
                dot = __fadd_rn(dot, __ldcg(&g_vopart[t & 1][b_own][h2][lane]));
            vo = __fmaf_rn(c_KAPPA, vo, dot);
            out[((size_t)(t + 1) * BSZ + b_own) * OO + lane] = vo;
        }
        __syncthreads();
    }

    // ---- global completion barrier, then softmax ----
    __threadfence();
    __syncthreads();
    if (tid == 0) {
        atomicAdd(&g_bar2, 1);
        while (*((volatile int*)&g_bar2) < HSLICES * NBG) __nanosleep(200);
        __threadfence();
    }
    __syncthreads();

    for (int i = w; i < 256; i += 16) {
        const int r = bid * 256 + i;                 // row over T_ALL*BSZ
        float* pr = out + (size_t)r * OO;
        float vv = (lane < OO) ? pr[lane] : -INFINITY;
        float m = vv;
#pragma unroll
        for (int off = 16; off > 0; off >>= 1)
            m = fmaxf(m, __shfl_xor_sync(0xffffffff, m, off));
        float e = (lane < OO) ? expf(vv - m) : 0.f;
        float sm = e;
#pragma unroll
        for (int off = 16; off > 0; off >>= 1)
            sm += __shfl_xor_sync(0xffffffff, sm, off);
        if (lane < OO) pr[lane] = e / sm;
    }
}

// ============================================================
extern "C" void kernel_launch(void* const* d_in, const int* in_sizes, int n_in,
                              void* d_out, int out_size) {
    const float* x     = (const float*)d_in[0];
    const float* w_in  = (const float*)d_in[1];
    const float* w_rec = (const float*)d_in[2];
    const float* w_out = (const float*)d_in[3];
    float* out = (float*)d_out;

    prep_k<<<512, 256>>>(w_rec, w_out);                                // 1
    init_k<<<256, 256>>>(out);                                         // 2
    in_gemm<<<dim3(HH / 128, (T_STEPS * BSZ) / 128), 256>>>(x, w_in);  // 3
    dummy_k<<<1, 32>>>();                                              // 4
    dummy_k<<<1, 32>>>();                                              // 5
    step_all<<<HSLICES * NBG, 512>>>(out);                             // 6 <- ncu -s 5
}

// round 17
// speedup vs baseline: 1.3970x; 1.3970x over previous
#include <cuda_runtime.h>
#include <math.h>

#define T_ALL 128
#define T_STEPS 127
#define BSZ 256
#define DD 512
#define HH 1024
#define OO 20
#define KC 320
#define HS 4                      // h slices (256 cols each)
#define NBG 32                    // batch groups
#define BPB 8                     // batch rows per block
#define CPS 256                   // cols per slice

__device__ __constant__ float c_ALPHA = 0.95122942450071400909f;
__device__ __constant__ float c_KAPPA = 0.95122942450071400909f;
#define THRv 1.0f

// ---- scratch ----
__device__ float    g_xin[(size_t)T_STEPS * BSZ * HH];
__device__ float    g_WT[HH * HH];            // WT[j][h], diag zeroed
__device__ float    g_WoT[HH * OO];           // WoT[h][o]
__device__ unsigned g_zbits[2][BSZ][HH / 32];
__device__ float    g_vopart[2][BSZ][HS][OO];
__device__ int      g_bar[NBG];
__device__ int      g_bar2;

#define FMA2(d_, a_, b_) \
    asm("fma.rn.f32x2 %0, %1, %2, %3;" : "=l"(d_) : "l"(a_), "l"(b_), "l"(d_))
#define PACK2(d_, x_) \
    asm("mov.b64 %0, {%1, %1};" : "=l"(d_) : "f"(x_))

__device__ __forceinline__ float2 unpack2(unsigned long long u) {
    float2 f;
    asm("mov.b64 {%0, %1}, %2;" : "=f"(f.x), "=f"(f.y) : "l"(u));
    return f;
}

__global__ void dummy_k() {}

// ============================================================
__global__ void __launch_bounds__(256) prep_k(const float* __restrict__ w_rec,
                                              const float* __restrict__ w_out) {
    int idx = blockIdx.x * 256 + threadIdx.x;
    int stride = gridDim.x * 256;
    for (int i = idx; i < HH * HH; i += stride) {
        int j = i / HH, h = i % HH;
        g_WT[i] = (h == j) ? 0.0f : w_rec[(size_t)h * HH + j];
    }
    for (int i = idx; i < HH * OO; i += stride) {
        int h = i / OO, o = i % OO;
        g_WoT[i] = w_out[(size_t)o * HH + h];
    }
}

// ============================================================
__global__ void __launch_bounds__(256) init_k(float* __restrict__ out) {
    int i = blockIdx.x * blockDim.x + threadIdx.x;
    int stride = gridDim.x * blockDim.x;
    for (int idx = i; idx < BSZ * (HH / 32); idx += stride)
        ((unsigned*)g_zbits[0])[idx] = 0u;
    for (int idx = i; idx < BSZ * OO; idx += stride)
        out[idx] = 0.f;
    if (i < NBG) g_bar[i] = 0;
    if (i == NBG) g_bar2 = 0;
}

// ============================================================
// input GEMM (R12, proven: bit-exact ascending-k chain, kc=320 fold)
// ============================================================
__global__ void __launch_bounds__(256) in_gemm(const float* __restrict__ x,
                                               const float* __restrict__ w_in) {
    __shared__ __align__(16) float As[2][8][128];
    __shared__ __align__(16) float Bs[2][8][128];
    const int tid = threadIdx.x;
    const int m0 = blockIdx.y * 128;
    const int n0 = blockIdx.x * 128;

    const int lr = tid >> 1;
    const int lk = (tid & 1) * 4;
    const int tm = (tid >> 4) * 4;
    const int tn = (tid & 15) * 4;

    const float* Ap = x + (size_t)(m0 + lr) * DD + lk;
    const float* Bp = w_in + (size_t)(n0 + lr) * DD + lk;

    float4 a  = __ldcs((const float4*)Ap);
    float4 bb = *(const float4*)Bp;
    As[0][lk + 0][lr] = a.x;  As[0][lk + 1][lr] = a.y;
    As[0][lk + 2][lr] = a.z;  As[0][lk + 3][lr] = a.w;
    Bs[0][lk + 0][lr] = bb.x; Bs[0][lk + 1][lr] = bb.y;
    Bs[0][lk + 2][lr] = bb.z; Bs[0][lk + 3][lr] = bb.w;
    __syncthreads();

    unsigned long long acc2[8][4];
#pragma unroll
    for (int i = 0; i < 8; i++)
#pragma unroll
        for (int j = 0; j < 4; j++) acc2[i][j] = 0ULL;

    int s = 0;
    for (int k0 = 0; k0 < DD; k0 += 8) {
        const int nk = k0 + 8;
        if (nk < DD) {
            a  = __ldcs((const float4*)(Ap + nk));
            bb = *(const float4*)(Bp + nk);
        }
#pragma unroll
        for (int d = 0; d < 8; d++) {
            float4 alo = *(const float4*)(&As[s][d][tm]);
            float4 ahi = *(const float4*)(&As[s][d][tm + 64]);
            ulonglong2 bl = *(const ulonglong2*)(&Bs[s][d][tn]);
            ulonglong2 bh = *(const ulonglong2*)(&Bs[s][d][tn + 64]);
            unsigned long long aa[8], bv[4] = {bl.x, bl.y, bh.x, bh.y};
            PACK2(aa[0], alo.x); PACK2(aa[1], alo.y);
            PACK2(aa[2], alo.z); PACK2(aa[3], alo.w);
            PACK2(aa[4], ahi.x); PACK2(aa[5], ahi.y);
            PACK2(aa[6], ahi.z); PACK2(aa[7], ahi.w);
#pragma unroll
            for (int i = 0; i < 8; i++)
#pragma unroll
                for (int j = 0; j < 4; j++)
                    FMA2(acc2[i][j], aa[i], bv[j]);
        }
        if (nk == KC) {
#pragma unroll
            for (int i = 0; i < 8; i++) {
                const int mr = m0 + tm + (i & 3) + ((i >> 2) << 6);
                float2 u0 = unpack2(acc2[i][0]), u1 = unpack2(acc2[i][1]);
                float2 u2 = unpack2(acc2[i][2]), u3 = unpack2(acc2[i][3]);
                float* dst = g_xin + (size_t)mr * HH + n0 + tn;
                *(float4*)dst        = make_float4(u0.x, u0.y, u1.x, u1.y);
                *(float4*)(dst + 64) = make_float4(u2.x, u2.y, u3.x, u3.y);
#pragma unroll
                for (int j = 0; j < 4; j++) acc2[i][j] = 0ULL;
            }
        }
        if (nk < DD) {
            As[s ^ 1][lk + 0][lr] = a.x;  As[s ^ 1][lk + 1][lr] = a.y;
            As[s ^ 1][lk + 2][lr] = a.z;  As[s ^ 1][lk + 3][lr] = a.w;
            Bs[s ^ 1][lk + 0][lr] = bb.x; Bs[s ^ 1][lk + 1][lr] = bb.y;
            Bs[s ^ 1][lk + 2][lr] = bb.z; Bs[s ^ 1][lk + 3][lr] = bb.w;
        }
        __syncthreads();
        s ^= 1;
    }

#pragma unroll
    for (int i = 0; i < 8; i++) {
        const int mr = m0 + tm + (i & 3) + ((i >> 2) << 6);
        float* dst = g_xin + (size_t)mr * HH + n0 + tn;
        float4 p0 = *(const float4*)dst;
        float4 p1 = *(const float4*)(dst + 64);
        float2 u0 = unpack2(acc2[i][0]), u1 = unpack2(acc2[i][1]);
        float2 u2 = unpack2(acc2[i][2]), u3 = unpack2(acc2[i][3]);
        float4 o0, o1;
        o0.x = __fadd_rn(p0.x, u0.x); o0.y = __fadd_rn(p0.y, u0.y);
        o0.z = __fadd_rn(p0.z, u1.x); o0.w = __fadd_rn(p0.w, u1.y);
        o1.x = __fadd_rn(p1.x, u2.x); o1.y = __fadd_rn(p1.y, u2.y);
        o1.z = __fadd_rn(p1.z, u3.x); o1.w = __fadd_rn(p1.w, u3.y);
        __stcs((float4*)dst, o0);
        __stcs((float4*)(dst + 64), o1);
    }
}

// ============================================================
// step kernel: 128 blocks = 32 bg x 4 hs; block = 8 b x 256 cols.
// Group g (64 thr) owns b = bg*8+g; thread covers 4 cols (float4).
// Per step: one warp per group builds b's ascending list (+ panel
// offsets at words 10/20/30); group walks list with MLP-4 batching
// (bit-exact chains, folds at 320/640/960). Cross-group L1 reuse of
// WT rows. z bitmask exchange + per-bg 4-block barrier per step.
// ============================================================
__global__ void __launch_bounds__(512) step_all(float* __restrict__ out) {
    const int bid = blockIdx.x;
    const int hs = bid & (HS - 1);
    const int bg = bid >> 2;
    const int tid = threadIdx.x;
    const int lane = tid & 31, wid = tid >> 5;
    const int g = tid >> 6;            // group 0..7
    const int tau = tid & 63;          // thread in group
    const int b = bg * BPB + g;
    const int h0 = hs * CPS + tau * 4;

    __shared__ unsigned short s_list[BPB][HH];
    __shared__ int s_po[BPB][5];
    __shared__ unsigned s_myz[BPB][8];

    float v0 = 0.f, v1 = 0.f, v2 = 0.f, v3 = 0.f;
    float vo = 0.f;                    // only hs==0, tau<OO

    for (int t = 0; t < T_STEPS; t++) {
        // ---- list build: even warps (one per group), lanes = words ----
        if ((wid & 1) == 0) {
            const int gg = wid >> 1;
            const int bb = bg * BPB + gg;
            unsigned w = __ldcg(&g_zbits[t & 1][bb][lane]);
            const int cnt = __popc(w);
            int sc = cnt;
#pragma unroll
            for (int o = 1; o < 32; o <<= 1) {
                int u = __shfl_up_sync(0xffffffffu, sc, o);
                if (lane >= o) sc += u;
            }
            if (lane == 9)  s_po[gg][1] = sc;
            if (lane == 19) s_po[gg][2] = sc;
            if (lane == 29) s_po[gg][3] = sc;
            if (lane == 31) { s_po[gg][4] = sc; s_po[gg][0] = 0; }
            int ofs = sc - cnt;
            const int base = lane * 32;
            while (w) {
                int i = __ffs(w) - 1; w &= w - 1;
                s_list[gg][ofs++] = (unsigned short)(base + i);
            }
        }
        __syncthreads();

        // hoisted xin
        const float4 xi = __ldcs((const float4*)(g_xin + (size_t)t * BSZ * HH
                                                 + (size_t)b * HH + h0));

        // ---- list walk: exact ascending chains, panel folds ----
        float tt0 = 0.f, tt1 = 0.f, tt2 = 0.f, tt3 = 0.f;
#pragma unroll 1
        for (int p = 0; p < 4; p++) {
            const int beg = s_po[g][p], end = s_po[g][p + 1];
            float a0 = 0.f, a1 = 0.f, a2 = 0.f, a3 = 0.f;
            int i = beg;
            for (; i + 4 <= end; i += 4) {
                float4 w0 = *(const float4*)(g_WT + (size_t)s_list[g][i + 0] * HH + h0);
                float4 w1 = *(const float4*)(g_WT + (size_t)s_list[g][i + 1] * HH + h0);
                float4 w2 = *(const float4*)(g_WT + (size_t)s_list[g][i + 2] * HH + h0);
                float4 w3 = *(const float4*)(g_WT + (size_t)s_list[g][i + 3] * HH + h0);
                a0 = __fadd_rn(a0, w0.x); a1 = __fadd_rn(a1, w0.y);
                a2 = __fadd_rn(a2, w0.z); a3 = __fadd_rn(a3, w0.w);
                a0 = __fadd_rn(a0, w1.x); a1 = __fadd_rn(a1, w1.y);
                a2 = __fadd_rn(a2, w1.z); a3 = __fadd_rn(a3, w1.w);
                a0 = __fadd_rn(a0, w2.x); a1 = __fadd_rn(a1, w2.y);
                a2 = __fadd_rn(a2, w2.z); a3 = __fadd_rn(a3, w2.w);
                a0 = __fadd_rn(a0, w3.x); a1 = __fadd_rn(a1, w3.y);
                a2 = __fadd_rn(a2, w3.z); a3 = __fadd_rn(a3, w3.w);
            }
            for (; i < end; i++) {
                float4 w0 = *(const float4*)(g_WT + (size_t)s_list[g][i] * HH + h0);
                a0 = __fadd_rn(a0, w0.x); a1 = __fadd_rn(a1, w0.y);
                a2 = __fadd_rn(a2, w0.z); a3 = __fadd_rn(a3, w0.w);
            }
            tt0 = __fadd_rn(tt0, a0); tt1 = __fadd_rn(tt1, a1);
            tt2 = __fadd_rn(tt2, a2); tt3 = __fadd_rn(tt3, a3);
        }

        // ---- v update (identical arithmetic to R12) ----
        const float zp0 = (v0 > THRv) ? 1.f : 0.f;
        const float zp1 = (v1 > THRv) ? 1.f : 0.f;
        const float zp2 = (v2 > THRv) ? 1.f : 0.f;
        const float zp3 = (v3 > THRv) ? 1.f : 0.f;
        v0 = __fsub_rn(__fadd_rn(__fmaf_rn(c_ALPHA, v0, tt0), xi.x), zp0);
        v1 = __fsub_rn(__fadd_rn(__fmaf_rn(c_ALPHA, v1, tt1), xi.y), zp1);
        v2 = __fsub_rn(__fadd_rn(__fmaf_rn(c_ALPHA, v2, tt2), xi.z), zp2);
        v3 = __fsub_rn(__fadd_rn(__fmaf_rn(c_ALPHA, v3, tt3), xi.w), zp3);

        const bool z0 = v0 > THRv, z1 = v1 > THRv, z2 = v2 > THRv, z3 = v3 > THRv;

        // ---- pack z bits: 4 bits per thread, octet OR-reduce -> words ----
        unsigned bits = ((z0 ? 1u : 0u) | (z1 ? 2u : 0u) |
                         (z2 ? 4u : 0u) | (z3 ? 8u : 0u)) << ((tau & 7) * 4);
#pragma unroll
        for (int off = 1; off < 8; off <<= 1)
            bits |= __shfl_xor_sync(0xffffffffu, bits, off);
        if ((tau & 7) == 0) {
            const int wd = tau >> 3;                     // 0..7
            g_zbits[(t + 1) & 1][b][hs * 8 + wd] = bits;
            s_myz[g][wd] = bits;
        }
        __syncthreads();

        // ---- vo partials over this slice (order-free) ----
        if (tau < OO) {
            float acc = 0.f;
#pragma unroll
            for (int wd = 0; wd < 8; wd++) {
                unsigned m = s_myz[g][wd];
                const int hb = hs * CPS + wd * 32;
                while (m) {
                    int i = __ffs(m) - 1; m &= m - 1;
                    acc += g_WoT[(hb + i) * OO + tau];
                }
            }
            g_vopart[t & 1][b][hs][tau] = acc;
        }

        // ---- per-bg barrier (4 blocks) ----
        __threadfence();
        __syncthreads();
        if (tid == 0) {
            atomicAdd(&g_bar[bg], 1);
            while (((volatile int*)g_bar)[bg] < HS * (t + 1)) __nanosleep(60);
            __threadfence();
        }
        __syncthreads();

        // ---- owner (hs 0) folds vo partials, writes out ----
        if (hs == 0 && tau < OO) {
            float dot = 0.f;
#pragma unroll
            for (int s2 = 0; s2 < HS; s2++)
                dot = __fadd_rn(dot, __ldcg(&g_vopart[t & 1][b][s2][tau]));
            vo = __fmaf_rn(c_KAPPA, vo, dot);
            out[((size_t)(t + 1) * BSZ + b) * OO + tau] = vo;
        }
        __syncthreads();
    }

    // ---- global barrier, then softmax (block handles 256 rows) ----
    __threadfence();
    __syncthreads();
    if (tid == 0) {
        atomicAdd(&g_bar2, 1);
        while (*((volatile int*)&g_bar2) < HS * NBG) __nanosleep(200);
        __threadfence();
    }
    __syncthreads();

    for (int i = wid; i < 256; i += 16) {
        const int r = bid * 256 + i;
        float* pr = out + (size_t)r * OO;
        float vv = (lane < OO) ? pr[lane] : -INFINITY;
        float m = vv;
#pragma unroll
        for (int off = 16; off > 0; off >>= 1)
            m = fmaxf(m, __shfl_xor_sync(0xffffffff, m, off));
        float e = (lane < OO) ? expf(vv - m) : 0.f;
        float sm = e;
#pragma unroll
        for (int off = 16; off > 0; off >>= 1)
            sm += __shfl_xor_sync(0xffffffff, sm, off);
        if (lane < OO) pr[lane] = e / sm;
    }
}

// ============================================================
extern "C" void kernel_launch(void* const* d_in, const int* in_sizes, int n_in,
                              void* d_out, int out_size) {
    const float* x     = (const float*)d_in[0];
    const float* w_in  = (const float*)d_in[1];
    const float* w_rec = (const float*)d_in[2];
    const float* w_out = (const float*)d_in[3];
    float* out = (float*)d_out;

    prep_k<<<512, 256>>>(w_rec, w_out);                                // 1
    init_k<<<256, 256>>>(out);                                         // 2
    in_gemm<<<dim3(HH / 128, (T_STEPS * BSZ) / 128), 256>>>(x, w_in);  // 3
    dummy_k<<<1, 32>>>();                                              // 4
    dummy_k<<<1, 32>>>();                                              // 5
    step_all<<<HS * NBG, 512>>>(out);                                  // 6 <- ncu -s 5
}